// round 10
// baseline (speedup 1.0000x reference)
#include <cuda_runtime.h>
#include <cstdint>
#include <math.h>

// Problem constants
#define DDIM   1024
#define NEXP   8
#define NTOK   8192
#define NPAIR  (NTOK * 2)

// GEMM tiling: CTA 128x128, 8 warps of 32x64, BK=32, 3-stage cp.async, 2 CTA/SM
#define BM 128
#define BN 128
#define BK 32
#define STAGES 3
#define A_BYTES (BM * BK * 4)              // 16384
#define B_BYTES (BN * BK * 4)              // 16384
#define STAGE_BYTES (A_BYTES + B_BYTES)    // 32768
#define SMEM_BYTES (STAGES * STAGE_BYTES)  // 98304

// -------- device scratch --------
__device__ float g_partial[(size_t)NPAIR * DDIM];   // 64 MB
__device__ float g_rdelta[(size_t)NTOK * DDIM];     // tf32-rounded, k16-permuted delta
__device__ float g_rW[(size_t)NEXP * DDIM * DDIM];  // tf32-rounded, k16-permuted expert_W
__device__ int   g_list[NEXP * NPAIR];
__device__ int   g_count[NEXP];
__device__ int   g_expert[NPAIR];
__device__ float g_weight[NPAIR];

// -------- helpers --------
__device__ __forceinline__ float to_tf32(float x) {
    uint32_t u;
    asm("cvt.rna.tf32.f32 %0, %1;" : "=r"(u) : "f"(x));
    return __uint_as_float(u);
}
__device__ __forceinline__ uint32_t smem_u32(const void* p) {
    uint32_t a;
    asm("{ .reg .u64 t; cvta.to.shared.u64 t, %1; cvt.u32.u64 %0, t; }" : "=r"(a) : "l"(p));
    return a;
}
__device__ __forceinline__ uint32_t swz128(uint32_t off) { return off ^ ((off >> 3) & 0x70u); }

__device__ __forceinline__ void cp_async16(uint32_t saddr, const void* gaddr) {
    asm volatile("cp.async.cg.shared.global [%0], [%1], 16;\n" :: "r"(saddr), "l"(gaddr));
}
__device__ __forceinline__ void cp_commit() { asm volatile("cp.async.commit_group;\n" ::: "memory"); }
template <int N>
__device__ __forceinline__ void cp_wait() { asm volatile("cp.async.wait_group %0;\n" :: "n"(N) : "memory"); }

__device__ __forceinline__ float4 lds128(uint32_t a) {
    float4 v;
    asm volatile("ld.shared.v4.f32 {%0,%1,%2,%3}, [%4];"
                 : "=f"(v.x), "=f"(v.y), "=f"(v.z), "=f"(v.w) : "r"(a));
    return v;
}

__device__ __forceinline__ void mma_tf32(float* c,
                                         float a0, float a1, float a2, float a3,
                                         float b0, float b1) {
    asm volatile(
        "mma.sync.aligned.m16n8k8.row.col.f32.tf32.tf32.f32 "
        "{%0,%1,%2,%3}, {%4,%5,%6,%7}, {%8,%9}, {%0,%1,%2,%3};\n"
        : "+f"(c[0]), "+f"(c[1]), "+f"(c[2]), "+f"(c[3])
        : "r"(__float_as_uint(a0)), "r"(__float_as_uint(a1)),
          "r"(__float_as_uint(a2)), "r"(__float_as_uint(a3)),
          "r"(__float_as_uint(b0)), "r"(__float_as_uint(b1)));
}

// -------- kernel 0: tf32 pre-round + k16 transpose permute --------
// Within each 16-float k-group: out[q*4+j] = tf32(in[j*4+q]).
__global__ void round_kernel(const float* __restrict__ src, float* __restrict__ dst, int n16) {
    int i = blockIdx.x * blockDim.x + threadIdx.x;
    if (i >= n16) return;
    const float4* s = (const float4*)(src + (size_t)i * 16);
    float4 i0 = s[0], i1 = s[1], i2 = s[2], i3 = s[3];
    float4* d = (float4*)(dst + (size_t)i * 16);
    float4 o;
    o.x = to_tf32(i0.x); o.y = to_tf32(i1.x); o.z = to_tf32(i2.x); o.w = to_tf32(i3.x); d[0] = o;
    o.x = to_tf32(i0.y); o.y = to_tf32(i1.y); o.z = to_tf32(i2.y); o.w = to_tf32(i3.y); d[1] = o;
    o.x = to_tf32(i0.z); o.y = to_tf32(i1.z); o.z = to_tf32(i2.z); o.w = to_tf32(i3.z); d[2] = o;
    o.x = to_tf32(i0.w); o.y = to_tf32(i1.w); o.z = to_tf32(i2.w); o.w = to_tf32(i3.w); d[3] = o;
}

// -------- kernel 1: gating (one warp per token) --------
__global__ void gate_kernel(const float* __restrict__ x,
                            const float* __restrict__ gw,
                            const float* __restrict__ gb) {
    int warp = (blockIdx.x * blockDim.x + threadIdx.x) >> 5;
    int lane = threadIdx.x & 31;
    if (warp >= NTOK) return;
    const float* xr = x + (size_t)warp * DDIM;

    float acc[NEXP];
#pragma unroll
    for (int e = 0; e < NEXP; e++) acc[e] = 0.f;
    for (int i = lane; i < DDIM; i += 32) {
        float v = xr[i];
#pragma unroll
        for (int e = 0; e < NEXP; e++) acc[e] += v * gw[e * DDIM + i];
    }
#pragma unroll
    for (int e = 0; e < NEXP; e++) {
#pragma unroll
        for (int o = 16; o > 0; o >>= 1) acc[e] += __shfl_xor_sync(0xffffffffu, acc[e], o);
    }
    if (lane == 0) {
        float logits[NEXP];
#pragma unroll
        for (int e = 0; e < NEXP; e++) logits[e] = acc[e] + gb[e];
        int i0 = 0; float v0 = logits[0];
#pragma unroll
        for (int e = 1; e < NEXP; e++) if (logits[e] > v0) { v0 = logits[e]; i0 = e; }
        int i1 = -1; float v1 = -3.4e38f;
#pragma unroll
        for (int e = 0; e < NEXP; e++) if (e != i0 && logits[e] > v1) { v1 = logits[e]; i1 = e; }
        float e1 = expf(v1 - v0);
        float inv = 1.0f / (1.0f + e1);
        g_expert[warp * 2 + 0] = i0;
        g_expert[warp * 2 + 1] = i1;
        g_weight[warp * 2 + 0] = inv;
        g_weight[warp * 2 + 1] = e1 * inv;
    }
}

// -------- kernel 2: grouping, one block per expert --------
#define GT   1024
#define GPER (NPAIR / GT)   // 16
__global__ void __launch_bounds__(GT) group_kernel() {
    const int e = blockIdx.x;
    const int t = threadIdx.x;
    const int warp = t >> 5;
    const int lane = t & 31;
    __shared__ int s_tot[32];

    const int base = t * GPER;
    unsigned mask = 0;
    int cnt = 0;
#pragma unroll
    for (int i = 0; i < GPER; i++) {
        if (g_expert[base + i] == e) { mask |= (1u << i); cnt++; }
    }
    int incl = cnt;
#pragma unroll
    for (int o = 1; o < 32; o <<= 1) {
        int u = __shfl_up_sync(0xffffffffu, incl, o);
        if (lane >= o) incl += u;
    }
    if (lane == 31) s_tot[warp] = incl;
    __syncthreads();
    if (warp == 0) {
        int v = s_tot[lane];
        int orig = v;
#pragma unroll
        for (int o = 1; o < 32; o <<= 1) {
            int u = __shfl_up_sync(0xffffffffu, v, o);
            if (lane >= o) v += u;
        }
        if (lane == 31) g_count[e] = v;
        s_tot[lane] = v - orig;
    }
    __syncthreads();

    int off = s_tot[warp] + incl - cnt;
    int* lst = g_list + e * NPAIR;
    while (mask) {
        int i = __ffs(mask) - 1;
        mask &= mask - 1;
        lst[off++] = base + i;
    }
}

// -------- kernel 3: grouped GEMM, tf32 mma.sync, LDS.128 frags, 2 CTA/SM --------
__global__ void __launch_bounds__(256, 2) gemm_kernel() {
    const int e   = blockIdx.z;
    const int cnt = g_count[e];
    const int m0  = blockIdx.y * BM;
    if (m0 >= cnt) return;
    const int n0  = blockIdx.x * BN;

    extern __shared__ __align__(1024) char smem[];
    __shared__ int s_pid[BM];
    __shared__ int s_tok[BM];

    const uint32_t smem_base = smem_u32(smem);
    const int tid = threadIdx.x;
    const int wid = tid >> 5;
    const int lane = tid & 31;
    const int warpM = wid & 3;    // 4 x 32-row bands
    const int warpN = wid >> 2;   // 2 x 64-col bands
    const int gid = lane >> 2;    // 0..7
    const int qid = lane & 3;     // 0..3

    if (tid < BM) {
        int p = (m0 + tid < cnt) ? g_list[e * NPAIR + m0 + tid] : -1;
        s_pid[tid] = p;
        s_tok[tid] = (p >= 0) ? (p >> 1) : 0;
    }
    __syncthreads();

    const float* __restrict__ Wb = g_rW + (size_t)e * DDIM * DDIM;
    const int NKB = DDIM / BK;  // 32

    auto issue_loads = [&](int kb) {
        const uint32_t sbase = smem_base + (uint32_t)(kb % STAGES) * STAGE_BYTES;
        const int kbase = kb * BK;
#pragma unroll
        for (int i = 0; i < 4; i++) {
            int idx = tid + i * 256;
            int r = idx >> 3, c4 = idx & 7;
            const float* g = g_rdelta + (size_t)s_tok[r] * DDIM + kbase + c4 * 4;
            cp_async16(sbase + swz128((uint32_t)(r * 128 + c4 * 16)), g);
        }
#pragma unroll
        for (int i = 0; i < 4; i++) {
            int idx = tid + i * 256;
            int r = idx >> 3, c4 = idx & 7;
            const float* g = Wb + (size_t)(n0 + r) * DDIM + kbase + c4 * 4;
            cp_async16(sbase + A_BYTES + swz128((uint32_t)(r * 128 + c4 * 16)), g);
        }
        cp_commit();
    };

    // Permuted-fragment addressing (validated in R8):
    // stored chunk c4 of row r sits at r*128 + (c4*16 ^ ((r&7)<<4)); reads use
    // c4 = kg*4 + qid and all rows have r&7 == gid. Column offsets live in
    // bits 4..6, row bases in bits >=7, so '+' is carry-free.
    const uint32_t g4 = (uint32_t)gid << 4;
    const uint32_t okg0 = ((uint32_t)(qid * 16)) ^ g4;        // kg = 0
    const uint32_t okg1 = ((uint32_t)(64 + qid * 16)) ^ g4;   // kg = 1
    uint32_t abase[4], bbase[8];
#pragma unroll
    for (int i = 0; i < 4; i++)
        abase[i] = (uint32_t)((warpM * 32 + i * 8 + gid) * 128);   // rows gid, +8, +16, +24
#pragma unroll
    for (int nt = 0; nt < 8; nt++)
        bbase[nt] = (uint32_t)(A_BYTES + (warpN * 64 + nt * 8 + gid) * 128);

    float acc[2][8][4];
#pragma unroll
    for (int mt = 0; mt < 2; mt++)
#pragma unroll
        for (int nt = 0; nt < 8; nt++)
#pragma unroll
            for (int j = 0; j < 4; j++) acc[mt][nt][j] = 0.f;

    issue_loads(0);
    issue_loads(1);

    for (int kb = 0; kb < NKB; kb++) {
        if (kb + 2 < NKB) cp_wait<1>(); else cp_wait<0>();
        __syncthreads();
        if (kb + 2 < NKB) issue_loads(kb + 2);

        const uint32_t sbase = smem_base + (uint32_t)(kb % STAGES) * STAGE_BYTES;

#pragma unroll
        for (int kg = 0; kg < 2; kg++) {
            const uint32_t col = sbase + (kg ? okg1 : okg0);
            // A fragments: 4 rows x one LDS.128 = orig k {qid,qid+4,qid+8,qid+12}+16kg
            float4 va[4];
#pragma unroll
            for (int i = 0; i < 4; i++) va[i] = lds128(col + abase[i]);
#pragma unroll
            for (int nt = 0; nt < 8; nt++) {
                const float4 vb = lds128(col + bbase[nt]);
#pragma unroll
                for (int mt = 0; mt < 2; mt++) {
                    const float4 u0 = va[mt * 2 + 0];
                    const float4 u1 = va[mt * 2 + 1];
                    mma_tf32(acc[mt][nt], u0.x, u1.x, u0.y, u1.y, vb.x, vb.y);
                    mma_tf32(acc[mt][nt], u0.z, u1.z, u0.w, u1.w, vb.z, vb.w);
                }
            }
        }
    }

    // epilogue
#pragma unroll
    for (int mt = 0; mt < 2; mt++) {
        int r0 = warpM * 32 + mt * 16 + gid;
        int r1 = r0 + 8;
        int p0 = s_pid[r0];
        int p1 = s_pid[r1];
#pragma unroll
        for (int nt = 0; nt < 8; nt++) {
            int c = n0 + warpN * 64 + nt * 8 + qid * 2;
            if (p0 >= 0)
                *(float2*)(g_partial + (size_t)p0 * DDIM + c) =
                    make_float2(acc[mt][nt][0], acc[mt][nt][1]);
            if (p1 >= 0)
                *(float2*)(g_partial + (size_t)p1 * DDIM + c) =
                    make_float2(acc[mt][nt][2], acc[mt][nt][3]);
        }
    }
}

// -------- kernel 4: weighted combine with expert bias --------
__global__ void combine_kernel(const float* __restrict__ eb, float* __restrict__ out) {
    int i   = blockIdx.x * blockDim.x + threadIdx.x;
    int tok = i >> 8;
    int c4  = i & 255;
    float w0 = g_weight[tok * 2 + 0], w1 = g_weight[tok * 2 + 1];
    int   e0 = g_expert[tok * 2 + 0], e1 = g_expert[tok * 2 + 1];

    float4 p0 = ((const float4*)(g_partial + (size_t)(tok * 2 + 0) * DDIM))[c4];
    float4 p1 = ((const float4*)(g_partial + (size_t)(tok * 2 + 1) * DDIM))[c4];
    float4 b0 = ((const float4*)(eb + (size_t)e0 * DDIM))[c4];
    float4 b1 = ((const float4*)(eb + (size_t)e1 * DDIM))[c4];

    float4 r;
    r.x = w0 * (p0.x + b0.x) + w1 * (p1.x + b1.x);
    r.y = w0 * (p0.y + b0.y) + w1 * (p1.y + b1.y);
    r.z = w0 * (p0.z + b0.z) + w1 * (p1.z + b1.z);
    r.w = w0 * (p0.w + b0.w) + w1 * (p1.w + b1.w);
    ((float4*)out)[i] = r;
}

// -------- launch --------
extern "C" void kernel_launch(void* const* d_in, const int* in_sizes, int n_in,
                              void* d_out, int out_size) {
    const float* input_feat = (const float*)d_in[0];
    const float* delta      = (const float*)d_in[1];
    const float* gate_W     = (const float*)d_in[2];
    const float* gate_b     = (const float*)d_in[3];
    const float* expert_W   = (const float*)d_in[4];
    const float* expert_b   = (const float*)d_in[5];
    float* out = (float*)d_out;

    cudaFuncSetAttribute(gemm_kernel, cudaFuncAttributeMaxDynamicSharedMemorySize, SMEM_BYTES);

    float* rdelta; cudaGetSymbolAddress((void**)&rdelta, g_rdelta);
    float* rW;     cudaGetSymbolAddress((void**)&rW, g_rW);

    round_kernel<<<(NTOK * DDIM / 16) / 256, 256>>>(delta, rdelta, NTOK * DDIM / 16);
    round_kernel<<<(NEXP * DDIM * DDIM / 16) / 256, 256>>>(expert_W, rW, NEXP * DDIM * DDIM / 16);
    gate_kernel<<<NTOK / 8, 256>>>(input_feat, gate_W, gate_b);
    group_kernel<<<NEXP, GT>>>();
    dim3 grid(DDIM / BN, NPAIR / BM, NEXP);
    gemm_kernel<<<grid, 256, SMEM_BYTES>>>();
    combine_kernel<<<(NTOK * (DDIM / 4)) / 256, 256>>>(expert_b, out);
}

// round 11
// speedup vs baseline: 1.3418x; 1.3418x over previous
#include <cuda_runtime.h>
#include <cstdint>
#include <math.h>

// Problem constants
#define DDIM   1024
#define NEXP   8
#define NTOK   8192
#define NPAIR  (NTOK * 2)

// GEMM tiling: CTA 128x128, 8 warps of 32x64, BK=32, 3-stage cp.async, 2 CTA/SM
#define BM 128
#define BN 128
#define BK 32
#define STAGES 3
#define A_BYTES (BM * BK * 4)              // 16384
#define B_BYTES (BN * BK * 4)              // 16384
#define STAGE_BYTES (A_BYTES + B_BYTES)    // 32768
#define SMEM_BYTES (STAGES * STAGE_BYTES)  // 98304

// -------- device scratch --------
__device__ float g_rdelta[(size_t)NTOK * DDIM];     // tf32-rounded delta
__device__ float g_rW[(size_t)NEXP * DDIM * DDIM];  // tf32-rounded expert_W
__device__ int   g_list[NEXP * NPAIR];
__device__ int   g_count[NEXP];
__device__ int   g_expert[NPAIR];
__device__ float g_weight[NPAIR];

// -------- helpers --------
__device__ __forceinline__ float to_tf32(float x) {
    uint32_t u;
    asm("cvt.rna.tf32.f32 %0, %1;" : "=r"(u) : "f"(x));
    return __uint_as_float(u);
}
__device__ __forceinline__ uint32_t smem_u32(const void* p) {
    uint32_t a;
    asm("{ .reg .u64 t; cvta.to.shared.u64 t, %1; cvt.u32.u64 %0, t; }" : "=r"(a) : "l"(p));
    return a;
}
__device__ __forceinline__ uint32_t swz128(uint32_t off) { return off ^ ((off >> 3) & 0x70u); }

__device__ __forceinline__ void cp_async16(uint32_t saddr, const void* gaddr) {
    asm volatile("cp.async.cg.shared.global [%0], [%1], 16;\n" :: "r"(saddr), "l"(gaddr));
}
__device__ __forceinline__ void cp_commit() { asm volatile("cp.async.commit_group;\n" ::: "memory"); }
template <int N>
__device__ __forceinline__ void cp_wait() { asm volatile("cp.async.wait_group %0;\n" :: "n"(N) : "memory"); }

__device__ __forceinline__ float lds32(uint32_t a) {
    float v;
    asm volatile("ld.shared.f32 %0, [%1];" : "=f"(v) : "r"(a));
    return v;
}
__device__ __forceinline__ void red_add_f32(float* gptr, float v) {
    asm volatile("red.global.add.f32 [%0], %1;" :: "l"(gptr), "f"(v) : "memory");
}

__device__ __forceinline__ void mma_tf32(float* c, const float* a, const float* b) {
    asm volatile(
        "mma.sync.aligned.m16n8k8.row.col.f32.tf32.tf32.f32 "
        "{%0,%1,%2,%3}, {%4,%5,%6,%7}, {%8,%9}, {%0,%1,%2,%3};\n"
        : "+f"(c[0]), "+f"(c[1]), "+f"(c[2]), "+f"(c[3])
        : "r"(__float_as_uint(a[0])), "r"(__float_as_uint(a[1])),
          "r"(__float_as_uint(a[2])), "r"(__float_as_uint(a[3])),
          "r"(__float_as_uint(b[0])), "r"(__float_as_uint(b[1])));
}

// -------- kernel 0: tf32 pre-round, both tensors in one launch --------
#define ND4 (NTOK * DDIM / 4)               // delta float4 count
#define NW4 (NEXP * DDIM * DDIM / 4)        // W float4 count
__global__ void round_kernel(const float* __restrict__ delta, float* __restrict__ rdelta,
                             const float* __restrict__ W, float* __restrict__ rW) {
    int i = blockIdx.x * blockDim.x + threadIdx.x;
    const float4* s;
    float4* d;
    if (i < ND4) { s = (const float4*)delta + i; d = (float4*)rdelta + i; }
    else         { int j = i - ND4; if (j >= NW4) return; s = (const float4*)W + j; d = (float4*)rW + j; }
    float4 v = *s;
    v.x = to_tf32(v.x); v.y = to_tf32(v.y); v.z = to_tf32(v.z); v.w = to_tf32(v.w);
    *d = v;
}

// -------- kernel 1: gating (one warp per token) --------
__global__ void gate_kernel(const float* __restrict__ x,
                            const float* __restrict__ gw,
                            const float* __restrict__ gb) {
    int warp = (blockIdx.x * blockDim.x + threadIdx.x) >> 5;
    int lane = threadIdx.x & 31;
    if (warp >= NTOK) return;
    const float* xr = x + (size_t)warp * DDIM;

    float acc[NEXP];
#pragma unroll
    for (int e = 0; e < NEXP; e++) acc[e] = 0.f;
    for (int i = lane; i < DDIM; i += 32) {
        float v = xr[i];
#pragma unroll
        for (int e = 0; e < NEXP; e++) acc[e] += v * gw[e * DDIM + i];
    }
#pragma unroll
    for (int e = 0; e < NEXP; e++) {
#pragma unroll
        for (int o = 16; o > 0; o >>= 1) acc[e] += __shfl_xor_sync(0xffffffffu, acc[e], o);
    }
    if (lane == 0) {
        float logits[NEXP];
#pragma unroll
        for (int e = 0; e < NEXP; e++) logits[e] = acc[e] + gb[e];
        int i0 = 0; float v0 = logits[0];
#pragma unroll
        for (int e = 1; e < NEXP; e++) if (logits[e] > v0) { v0 = logits[e]; i0 = e; }
        int i1 = -1; float v1 = -3.4e38f;
#pragma unroll
        for (int e = 0; e < NEXP; e++) if (e != i0 && logits[e] > v1) { v1 = logits[e]; i1 = e; }
        float e1 = expf(v1 - v0);
        float inv = 1.0f / (1.0f + e1);
        g_expert[warp * 2 + 0] = i0;
        g_expert[warp * 2 + 1] = i1;
        g_weight[warp * 2 + 0] = inv;
        g_weight[warp * 2 + 1] = e1 * inv;
    }
}

// -------- kernel 2: grouping, one block per expert --------
#define GT   1024
#define GPER (NPAIR / GT)   // 16
__global__ void __launch_bounds__(GT) group_kernel() {
    const int e = blockIdx.x;
    const int t = threadIdx.x;
    const int warp = t >> 5;
    const int lane = t & 31;
    __shared__ int s_tot[32];

    const int base = t * GPER;
    unsigned mask = 0;
    int cnt = 0;
#pragma unroll
    for (int i = 0; i < GPER; i++) {
        if (g_expert[base + i] == e) { mask |= (1u << i); cnt++; }
    }
    int incl = cnt;
#pragma unroll
    for (int o = 1; o < 32; o <<= 1) {
        int u = __shfl_up_sync(0xffffffffu, incl, o);
        if (lane >= o) incl += u;
    }
    if (lane == 31) s_tot[warp] = incl;
    __syncthreads();
    if (warp == 0) {
        int v = s_tot[lane];
        int orig = v;
#pragma unroll
        for (int o = 1; o < 32; o <<= 1) {
            int u = __shfl_up_sync(0xffffffffu, v, o);
            if (lane >= o) v += u;
        }
        if (lane == 31) g_count[e] = v;
        s_tot[lane] = v - orig;
    }
    __syncthreads();

    int off = s_tot[warp] + incl - cnt;
    int* lst = g_list + e * NPAIR;
    while (mask) {
        int i = __ffs(mask) - 1;
        mask &= mask - 1;
        lst[off++] = base + i;
    }
}

// -------- kernel 3: grouped GEMM (R9 mainloop) + fused weighted epilogue --------
__global__ void __launch_bounds__(256, 2) gemm_kernel(const float* __restrict__ eb,
                                                      float* __restrict__ out) {
    const int e   = blockIdx.z;
    const int cnt = g_count[e];
    const int m0  = blockIdx.y * BM;
    if (m0 >= cnt) return;
    const int n0  = blockIdx.x * BN;

    extern __shared__ __align__(1024) char smem[];
    __shared__ int   s_pid[BM];
    __shared__ int   s_tok[BM];
    __shared__ float s_w[BM];

    const uint32_t smem_base = smem_u32(smem);
    const int tid = threadIdx.x;
    const int wid = tid >> 5;
    const int lane = tid & 31;
    const int warpM = wid & 3;    // 4 x 32-row bands
    const int warpN = wid >> 2;   // 2 x 64-col bands
    const int gid = lane >> 2;    // 0..7
    const int qid = lane & 3;     // 0..3

    if (tid < BM) {
        int p = (m0 + tid < cnt) ? g_list[e * NPAIR + m0 + tid] : -1;
        s_pid[tid] = p;
        s_tok[tid] = (p >= 0) ? (p >> 1) : 0;
        s_w[tid]   = (p >= 0) ? g_weight[p] : 0.f;
    }
    __syncthreads();

    const float* __restrict__ Wb = g_rW + (size_t)e * DDIM * DDIM;
    const int NKB = DDIM / BK;  // 32

    auto issue_loads = [&](int kb) {
        const uint32_t sbase = smem_base + (uint32_t)(kb % STAGES) * STAGE_BYTES;
        const int kbase = kb * BK;
#pragma unroll
        for (int i = 0; i < 4; i++) {
            int idx = tid + i * 256;
            int r = idx >> 3, c4 = idx & 7;
            const float* g = g_rdelta + (size_t)s_tok[r] * DDIM + kbase + c4 * 4;
            cp_async16(sbase + swz128((uint32_t)(r * 128 + c4 * 16)), g);
        }
#pragma unroll
        for (int i = 0; i < 4; i++) {
            int idx = tid + i * 256;
            int r = idx >> 3, c4 = idx & 7;
            const float* g = Wb + (size_t)(n0 + r) * DDIM + kbase + c4 * 4;
            cp_async16(sbase + A_BYTES + swz128((uint32_t)(r * 128 + c4 * 16)), g);
        }
        cp_commit();
    };

    // R9-proven fragment addressing: Q = r*128 + qid*4 | ((r&7)<<4), r&7==gid
    uint32_t qa[4], qb[8];
#pragma unroll
    for (int mt = 0; mt < 2; mt++) {
        int r0 = warpM * 32 + mt * 16 + gid;
        int r1 = r0 + 8;
        qa[mt * 2 + 0] = (uint32_t)(r0 * 128 + qid * 4) | (uint32_t)((r0 & 7) << 4);
        qa[mt * 2 + 1] = (uint32_t)(r1 * 128 + qid * 4) | (uint32_t)((r1 & 7) << 4);
    }
#pragma unroll
    for (int nt = 0; nt < 8; nt++) {
        int n = warpN * 64 + nt * 8 + gid;
        qb[nt] = (uint32_t)(A_BYTES + n * 128 + qid * 4) | (uint32_t)((n & 7) << 4);
    }

    float acc[2][8][4];
#pragma unroll
    for (int mt = 0; mt < 2; mt++)
#pragma unroll
        for (int nt = 0; nt < 8; nt++)
#pragma unroll
            for (int j = 0; j < 4; j++) acc[mt][nt][j] = 0.f;

    issue_loads(0);
    issue_loads(1);

    for (int kb = 0; kb < NKB; kb++) {
        if (kb + 2 < NKB) cp_wait<1>(); else cp_wait<0>();
        __syncthreads();
        if (kb + 2 < NKB) issue_loads(kb + 2);

        const uint32_t sbase = smem_base + (uint32_t)(kb % STAGES) * STAGE_BYTES;
        uint32_t QA[4], QB[8];
#pragma unroll
        for (int i = 0; i < 4; i++) QA[i] = sbase + qa[i];
#pragma unroll
        for (int i = 0; i < 8; i++) QB[i] = sbase + qb[i];

#pragma unroll
        for (int ks = 0; ks < 4; ks++) {
            const uint32_t c0 = (uint32_t)((2 * ks + 0) * 16);
            const uint32_t c1 = (uint32_t)((2 * ks + 1) * 16);
            float a[2][4];
#pragma unroll
            for (int mt = 0; mt < 2; mt++) {
                a[mt][0] = lds32(QA[mt * 2 + 0] ^ c0);
                a[mt][1] = lds32(QA[mt * 2 + 1] ^ c0);
                a[mt][2] = lds32(QA[mt * 2 + 0] ^ c1);
                a[mt][3] = lds32(QA[mt * 2 + 1] ^ c1);
            }
            float b[8][2];
#pragma unroll
            for (int nt = 0; nt < 8; nt++) {
                b[nt][0] = lds32(QB[nt] ^ c0);
                b[nt][1] = lds32(QB[nt] ^ c1);
            }
#pragma unroll
            for (int mt = 0; mt < 2; mt++)
#pragma unroll
                for (int nt = 0; nt < 8; nt++)
                    mma_tf32(acc[mt][nt], a[mt], b[nt]);
        }
    }

    // fused epilogue: out[tok, c] += w * (acc + bias[e, c])  (red.global, order-free for 2 terms)
#pragma unroll
    for (int mt = 0; mt < 2; mt++) {
        int r0 = warpM * 32 + mt * 16 + gid;
        int r1 = r0 + 8;
        int p0 = s_pid[r0];
        int p1 = s_pid[r1];
        float w0 = s_w[r0], w1 = s_w[r1];
        float* o0 = out + (size_t)s_tok[r0] * DDIM;
        float* o1 = out + (size_t)s_tok[r1] * DDIM;
#pragma unroll
        for (int nt = 0; nt < 8; nt++) {
            int c = n0 + warpN * 64 + nt * 8 + qid * 2;
            const float2 bv = *(const float2*)(eb + (size_t)e * DDIM + c);
            if (p0 >= 0) {
                red_add_f32(o0 + c + 0, w0 * (acc[mt][nt][0] + bv.x));
                red_add_f32(o0 + c + 1, w0 * (acc[mt][nt][1] + bv.y));
            }
            if (p1 >= 0) {
                red_add_f32(o1 + c + 0, w1 * (acc[mt][nt][2] + bv.x));
                red_add_f32(o1 + c + 1, w1 * (acc[mt][nt][3] + bv.y));
            }
        }
    }
}

// -------- launch --------
extern "C" void kernel_launch(void* const* d_in, const int* in_sizes, int n_in,
                              void* d_out, int out_size) {
    const float* input_feat = (const float*)d_in[0];
    const float* delta      = (const float*)d_in[1];
    const float* gate_W     = (const float*)d_in[2];
    const float* gate_b     = (const float*)d_in[3];
    const float* expert_W   = (const float*)d_in[4];
    const float* expert_b   = (const float*)d_in[5];
    float* out = (float*)d_out;

    cudaFuncSetAttribute(gemm_kernel, cudaFuncAttributeMaxDynamicSharedMemorySize, SMEM_BYTES);

    float* rdelta; cudaGetSymbolAddress((void**)&rdelta, g_rdelta);
    float* rW;     cudaGetSymbolAddress((void**)&rW, g_rW);

    cudaMemsetAsync(out, 0, (size_t)out_size * sizeof(float));
    round_kernel<<<(ND4 + NW4 + 255) / 256, 256>>>(delta, rdelta, expert_W, rW);
    gate_kernel<<<NTOK / 8, 256>>>(input_feat, gate_W, gate_b);
    group_kernel<<<NEXP, GT>>>();
    dim3 grid(DDIM / BN, NPAIR / BM, NEXP);
    gemm_kernel<<<grid, 256, SMEM_BYTES>>>(expert_b, out);
}